// round 4
// baseline (speedup 1.0000x reference)
#include <cuda_runtime.h>
#include <cuda_bf16.h>
#include <cstdint>
#include <math.h>

#define BATCH 16
#define ZD 256
#define OC 256
#define IC 128
#define FANIN (IC*9)          // 1152
#define NTOT (OC*FANIN)       // 294912
#define HW 64

// ---------------- device scratch (no allocation APIs) ----------------
__device__ float g_dw[BATCH*NTOT];                    // delta_w [b][n]
__device__ __nv_bfloat16 g_whi[BATCH*OC*9*IC];        // weights hi, [b][oc][tap][cin]
__device__ __nv_bfloat16 g_wlo[BATCH*OC*9*IC];        // weights lo

// mma.sync bf16 (sm_80-era PTX — valid on plain compute_103 virtual arch)
__device__ __forceinline__ void mma16816(float* d, const uint32_t* a,
                                         uint32_t b0, uint32_t b1) {
    asm volatile(
        "mma.sync.aligned.m16n8k16.row.col.f32.bf16.bf16.f32 "
        "{%0,%1,%2,%3}, {%4,%5,%6,%7}, {%8,%9}, {%0,%1,%2,%3};"
        : "+f"(d[0]), "+f"(d[1]), "+f"(d[2]), "+f"(d[3])
        : "r"(a[0]), "r"(a[1]), "r"(a[2]), "r"(a[3]), "r"(b0), "r"(b1));
}

// ---------------------------------------------------------------------------
// Kernel A: delta[b][n] = sum_k z[b][k] * head_w[n][k]
// Double-buffered hw staging: 1 barrier per K-tile, LDG(kt+1) hoisted
// above compute(kt) so L2/DRAM latency is hidden.
// ---------------------------------------------------------------------------
__global__ void __launch_bounds__(128) gemm_delta(const float* __restrict__ z,
                                                  const float* __restrict__ hw)
{
    __shared__ float z_s[BATCH][ZD];
    __shared__ float hw_s[2][8][260];

    const int tid = threadIdx.x;
    const int n0  = blockIdx.x * 256;

    {
        const float4* zg = (const float4*)z;
        float4* zs = (float4*)&z_s[0][0];
        #pragma unroll
        for (int f = tid; f < BATCH*ZD/4; f += 128) zs[f] = zg[f];
    }

    const int bg  = tid >> 6;
    const int nth = tid & 63;

    // thread's 4 staging slots: f = tid + i*128 -> row=f>>1, c4=f&1
    int srow[4], sc4[4];
    #pragma unroll
    for (int i = 0; i < 4; i++) { int f = tid + i*128; srow[i] = f >> 1; sc4[i] = f & 1; }

    // prologue: stage kt=0
    #pragma unroll
    for (int i = 0; i < 4; i++) {
        float4 v = *(const float4*)&hw[(size_t)(n0 + srow[i])*ZD + sc4[i]*4];
        hw_s[0][sc4[i]*4+0][srow[i]] = v.x;
        hw_s[0][sc4[i]*4+1][srow[i]] = v.y;
        hw_s[0][sc4[i]*4+2][srow[i]] = v.z;
        hw_s[0][sc4[i]*4+3][srow[i]] = v.w;
    }
    __syncthreads();

    float acc[8][4];
    #pragma unroll
    for (int i = 0; i < 8; i++)
        #pragma unroll
        for (int j = 0; j < 4; j++) acc[i][j] = 0.f;

    for (int kt = 0; kt < ZD/8; kt++) {
        // hoist next tile's LDG
        float4 nv[4];
        if (kt < ZD/8 - 1) {
            #pragma unroll
            for (int i = 0; i < 4; i++)
                nv[i] = *(const float4*)&hw[(size_t)(n0 + srow[i])*ZD + (kt+1)*8 + sc4[i]*4];
        }

        const int cb = kt & 1;
        #pragma unroll
        for (int k = 0; k < 8; k++) {
            float zr[8], hr[4];
            #pragma unroll
            for (int bi = 0; bi < 8; bi++) zr[bi] = z_s[bg*8+bi][kt*8+k];
            #pragma unroll
            for (int j = 0; j < 4; j++)  hr[j] = hw_s[cb][k][j*64 + nth];
            #pragma unroll
            for (int bi = 0; bi < 8; bi++)
                #pragma unroll
                for (int j = 0; j < 4; j++)
                    acc[bi][j] = fmaf(zr[bi], hr[j], acc[bi][j]);
        }

        if (kt < ZD/8 - 1) {
            const int nb = cb ^ 1;
            #pragma unroll
            for (int i = 0; i < 4; i++) {
                hw_s[nb][sc4[i]*4+0][srow[i]] = nv[i].x;
                hw_s[nb][sc4[i]*4+1][srow[i]] = nv[i].y;
                hw_s[nb][sc4[i]*4+2][srow[i]] = nv[i].z;
                hw_s[nb][sc4[i]*4+3][srow[i]] = nv[i].w;
            }
        }
        __syncthreads();
    }

    #pragma unroll
    for (int bi = 0; bi < 8; bi++)
        #pragma unroll
        for (int j = 0; j < 4; j++)
            g_dw[(size_t)(bg*8+bi)*NTOT + n0 + j*64 + nth] = acc[bi][j];
}

// ---------------------------------------------------------------------------
// Kernel B: standardize + build weights, emit bf16 hi/lo, [b][oc][tap][cin]
// ---------------------------------------------------------------------------
__global__ void __launch_bounds__(128) build_w(const float* __restrict__ base)
{
    const int b  = blockIdx.x >> 8;
    const int oc = blockIdx.x & 255;
    const int tid = threadIdx.x;

    const float* dwp = &g_dw[(size_t)b*NTOT + oc*FANIN];

    float v[9];
    float s = 0.f, sq = 0.f;
    #pragma unroll
    for (int t = 0; t < 9; t++) {
        v[t] = dwp[tid + t*128];
        s  += v[t];
        sq += v[t]*v[t];
    }
    #pragma unroll
    for (int off = 16; off; off >>= 1) {
        s  += __shfl_xor_sync(0xffffffffu, s,  off);
        sq += __shfl_xor_sync(0xffffffffu, sq, off);
    }
    __shared__ float ss[4], ssq[4];
    const int wid = tid >> 5;
    if ((tid & 31) == 0) { ss[wid] = s; ssq[wid] = sq; }
    __syncthreads();
    s  = ss[0] + ss[1] + ss[2] + ss[3];
    sq = ssq[0] + ssq[1] + ssq[2] + ssq[3];

    const float inv_n = 1.0f / (float)FANIN;
    float mu  = s * inv_n;
    float var = sq * inv_n - mu*mu;
    float rs  = rsqrtf(var + 1e-5f);
    const float inv_sqrt2 = 0.70710678118654752440f;
    float c1 = rs * sqrtf(2.0f / (float)FANIN) * inv_sqrt2;

    const float* bw = &base[(size_t)oc*FANIN];
    __nv_bfloat16* whi = &g_whi[(size_t)(b*OC + oc)*9*IC];
    __nv_bfloat16* wlo = &g_wlo[(size_t)(b*OC + oc)*9*IC];
    #pragma unroll
    for (int t = 0; t < 9; t++) {
        int i = tid + t*128;           // i = cin*9 + tap
        int cin = i / 9, tap = i - cin*9;
        float w = bw[i]*inv_sqrt2 + (v[t] - mu)*c1;
        __nv_bfloat16 hi = __float2bfloat16(w);
        __nv_bfloat16 lo = __float2bfloat16(w - __bfloat162float(hi));
        whi[tap*IC + cin] = hi;
        wlo[tap*IC + cin] = lo;
    }
}

// ---------------------------------------------------------------------------
// Kernel C: implicit-GEMM conv via mma.sync bf16 (hi/lo 3-pass, fp32 accum).
// CTA = (4 y-rows, 128-oc tile, b). 256 threads = 8 warps.
// Warp tile 64oc x 64n: mw=wid&1 -> 64-oc half; yl=wid>>1 -> one y-row.
// (Halves per-CTA LDS fragment traffic + barrier cost vs 16x(32x64).)
// ---------------------------------------------------------------------------
#define XS_STRIDE 144                  // bytes per (y,x) row of 64 cin bf16 (+16B pad)
#define XS_BYTES  (6*66*XS_STRIDE)     // 57024
#define SM_A_HI   0                    // 128 oc x 144B = 18432
#define SM_A_LO   18432
#define SM_XS_HI  36864
#define SM_XS_LO  (SM_XS_HI + XS_BYTES)     // 93888
#define CONV_SMEM (SM_XS_LO + XS_BYTES)     // 150912

__global__ void __launch_bounds__(256, 1) conv_mma(const float* __restrict__ x,
                                                   float* __restrict__ out)
{
    extern __shared__ char smem[];
    const int tid  = threadIdx.x;
    const int wid  = tid >> 5;
    const int lane = tid & 31;
    const int y0   = blockIdx.x * 4;
    const int oc0  = blockIdx.y * 128;
    const int b    = blockIdx.z;

    const int mw = wid & 1;       // oc half (64)
    const int yl = wid >> 1;      // local y row
    const int qr = lane >> 2;     // 0..7
    const int qc = lane & 3;      // 0..3

    float acc[4][8][4];
    #pragma unroll
    for (int mf = 0; mf < 4; mf++)
        #pragma unroll
        for (int nf = 0; nf < 8; nf++)
            #pragma unroll
            for (int q = 0; q < 4; q++) acc[mf][nf][q] = 0.f;

    // zero xs once (halo pads at x'=0/65 and OOB y rows stay zero)
    for (int i = tid; i < (2*XS_BYTES)/16; i += 256)
        *(uint4*)(smem + SM_XS_HI + i*16) = make_uint4(0u,0u,0u,0u);
    __syncthreads();

    for (int ch = 0; ch < 2; ch++) {
        // ---- stage x chunk: [6 y][66 x][64 cin] bf16 hi/lo, channels-last ----
        for (int i = tid; i < 6*64*16; i += 256) {
            int ys  = i >> 10;
            int rem = i & 1023;
            int c   = rem >> 4;
            int x4  = rem & 15;
            int gy  = y0 - 1 + ys;
            if (gy >= 0 && gy < HW) {
                const float4 v = *(const float4*)
                    &x[(((size_t)(b*IC + ch*64 + c)*HW) + gy)*HW + x4*4];
                float f[4] = {v.x, v.y, v.z, v.w};
                #pragma unroll
                for (int q = 0; q < 4; q++) {
                    __nv_bfloat16 hi = __float2bfloat16(f[q]);
                    __nv_bfloat16 lo = __float2bfloat16(f[q] - __bfloat162float(hi));
                    int off = (ys*66 + x4*4 + q + 1)*XS_STRIDE + c*2;
                    *(__nv_bfloat16*)(smem + SM_XS_HI + off) = hi;
                    *(__nv_bfloat16*)(smem + SM_XS_LO + off) = lo;
                }
            }
        }
        __syncthreads();

        for (int tap = 0; tap < 9; tap++) {
            const int r = tap / 3, s = tap - r*3;

            // ---- stage A: [128 oc][64 cin] hi/lo (rows padded to 144B) ----
            {
                const size_t abase = ((size_t)((b*OC + oc0)*9 + tap))*IC + (size_t)ch*64;
                for (int i = tid; i < 1024; i += 256) {
                    int row = i >> 3, j = i & 7;
                    size_t off8 = (abase + (size_t)row*(9*IC)) / 8 + j;   // uint4 index
                    uint4 vh = ((const uint4*)g_whi)[off8];
                    uint4 vl = ((const uint4*)g_wlo)[off8];
                    *(uint4*)(smem + SM_A_HI + row*XS_STRIDE + j*16) = vh;
                    *(uint4*)(smem + SM_A_LO + row*XS_STRIDE + j*16) = vl;
                }
            }
            __syncthreads();

            // ---- compute: K=64 over this (ch,tap) ----
            {
                const int a_row0 = (mw*64 + qr)*XS_STRIDE + qc*4;   // mf stride 16*144
                const int bbase  = ((yl + r)*66 + s + qr)*XS_STRIDE + qc*4;

                #pragma unroll
                for (int ks = 0; ks < 4; ks++) {
                    const int kb = ks*32;     // byte offset of k-step
                    uint32_t ah[4][4], al[4][4];
                    #pragma unroll
                    for (int mf = 0; mf < 4; mf++) {
                        const int ar = a_row0 + mf*(16*XS_STRIDE) + kb;
                        ah[mf][0] = *(const uint32_t*)(smem + SM_A_HI + ar);
                        ah[mf][1] = *(const uint32_t*)(smem + SM_A_HI + ar + 8*XS_STRIDE);
                        ah[mf][2] = *(const uint32_t*)(smem + SM_A_HI + ar + 16);
                        ah[mf][3] = *(const uint32_t*)(smem + SM_A_HI + ar + 8*XS_STRIDE + 16);
                        al[mf][0] = *(const uint32_t*)(smem + SM_A_LO + ar);
                        al[mf][1] = *(const uint32_t*)(smem + SM_A_LO + ar + 8*XS_STRIDE);
                        al[mf][2] = *(const uint32_t*)(smem + SM_A_LO + ar + 16);
                        al[mf][3] = *(const uint32_t*)(smem + SM_A_LO + ar + 8*XS_STRIDE + 16);
                    }
                    #pragma unroll
                    for (int nf = 0; nf < 8; nf++) {
                        const int ba = bbase + nf*(8*XS_STRIDE) + kb;
                        uint32_t bh0 = *(const uint32_t*)(smem + SM_XS_HI + ba);
                        uint32_t bh1 = *(const uint32_t*)(smem + SM_XS_HI + ba + 16);
                        uint32_t bl0 = *(const uint32_t*)(smem + SM_XS_LO + ba);
                        uint32_t bl1 = *(const uint32_t*)(smem + SM_XS_LO + ba + 16);
                        #pragma unroll
                        for (int mf = 0; mf < 4; mf++) {
                            mma16816(acc[mf][nf], ah[mf], bh0, bh1);
                            mma16816(acc[mf][nf], ah[mf], bl0, bl1);
                            mma16816(acc[mf][nf], al[mf], bh0, bh1);
                        }
                    }
                }
            }
            __syncthreads();   // protect A (and xs on last tap) before overwrite
        }
    }

    // ---- epilogue: d-frag -> gmem (float2 stores) ----
    const int y = y0 + yl;
    #pragma unroll
    for (int mf = 0; mf < 4; mf++) {
        const int oc = oc0 + mw*64 + mf*16 + qr;
        float* op0 = out + (((size_t)(b*OC + oc    )*HW) + y)*HW;
        float* op1 = out + (((size_t)(b*OC + oc + 8)*HW) + y)*HW;
        #pragma unroll
        for (int nf = 0; nf < 8; nf++) {
            const int xp = nf*8 + qc*2;
            *(float2*)&op0[xp] = make_float2(acc[mf][nf][0], acc[mf][nf][1]);
            *(float2*)&op1[xp] = make_float2(acc[mf][nf][2], acc[mf][nf][3]);
        }
    }
}

// ---------------------------------------------------------------------------
extern "C" void kernel_launch(void* const* d_in, const int* in_sizes, int n_in,
                              void* d_out, int out_size)
{
    const float* x    = (const float*)d_in[0];  // [16,128,64,64]
    const float* z    = (const float*)d_in[1];  // [16,256]
    const float* bw   = (const float*)d_in[2];  // [256,128,3,3]
    const float* hw   = (const float*)d_in[3];  // [294912,256]
    float*       out  = (float*)d_out;          // [16,256,64,64]

    static bool attr_set = false;
    if (!attr_set) {
        cudaFuncSetAttribute(conv_mma, cudaFuncAttributeMaxDynamicSharedMemorySize, CONV_SMEM);
        attr_set = true;
    }

    gemm_delta<<<NTOT/256, 128>>>(z, hw);
    build_w<<<BATCH*OC, 128>>>(bw);
    conv_mma<<<dim3(16, 2, BATCH), 256, CONV_SMEM>>>(x, out);
}

// round 5
// speedup vs baseline: 1.7555x; 1.7555x over previous
#include <cuda_runtime.h>
#include <cuda_fp16.h>
#include <cstdint>
#include <math.h>

#define BATCH 16
#define ZD 256
#define OC 256
#define IC 128
#define FANIN (IC*9)          // 1152
#define NTOT (OC*FANIN)       // 294912
#define HW 64

// ---------------- device scratch (no allocation APIs) ----------------
__device__ float g_dw[BATCH*NTOT];             // delta_w [b][n]
__device__ __half g_whi[BATCH*OC*9*IC];        // weights hi fp16, [b][oc][tap][cin]
__device__ __half g_wlo[BATCH*OC*9*IC];        // weights lo fp16

// fp16 mma.sync (sm_80-era PTX — valid on plain compute_103 virtual arch)
__device__ __forceinline__ void mma16816h(float* d, const uint32_t* a,
                                          uint32_t b0, uint32_t b1) {
    asm volatile(
        "mma.sync.aligned.m16n8k16.row.col.f32.f16.f16.f32 "
        "{%0,%1,%2,%3}, {%4,%5,%6,%7}, {%8,%9}, {%0,%1,%2,%3};"
        : "+f"(d[0]), "+f"(d[1]), "+f"(d[2]), "+f"(d[3])
        : "r"(a[0]), "r"(a[1]), "r"(a[2]), "r"(a[3]), "r"(b0), "r"(b1));
}

// ---------------------------------------------------------------------------
// Kernel A: delta[b][n] = sum_k z[b][k] * head_w[n][k]
// Pure streaming: thread owns 4 consecutive n, 16 batch accumulators;
// z broadcast from smem; k unrolled by 8 -> MLP 8 LDG.128 per thread.
// ---------------------------------------------------------------------------
__global__ void __launch_bounds__(256, 2) gemm_delta(const float* __restrict__ z,
                                                     const float* __restrict__ hw)
{
    __shared__ float z_s[BATCH][ZD];   // 16 KB
    const int tid = threadIdx.x;

    {
        const float4* zg = (const float4*)z;
        float4* zs = (float4*)&z_s[0][0];
        #pragma unroll
        for (int f = tid; f < BATCH*ZD/4; f += 256) zs[f] = zg[f];
    }
    __syncthreads();

    const int n0 = blockIdx.x * 1024 + tid * 4;

    float acc[16][4];
    #pragma unroll
    for (int bi = 0; bi < 16; bi++)
        #pragma unroll
        for (int j = 0; j < 4; j++) acc[bi][j] = 0.f;

    for (int k = 0; k < ZD; k += 8) {
        float4 h[4][2];
        #pragma unroll
        for (int j = 0; j < 4; j++) {
            h[j][0] = *(const float4*)&hw[(size_t)(n0 + j)*ZD + k];
            h[j][1] = *(const float4*)&hw[(size_t)(n0 + j)*ZD + k + 4];
        }
        #pragma unroll
        for (int bi = 0; bi < 16; bi++) {
            float4 z0 = *(const float4*)&z_s[bi][k];
            float4 z1 = *(const float4*)&z_s[bi][k + 4];
            #pragma unroll
            for (int j = 0; j < 4; j++) {
                float a = acc[bi][j];
                a = fmaf(h[j][0].x, z0.x, a);
                a = fmaf(h[j][0].y, z0.y, a);
                a = fmaf(h[j][0].z, z0.z, a);
                a = fmaf(h[j][0].w, z0.w, a);
                a = fmaf(h[j][1].x, z1.x, a);
                a = fmaf(h[j][1].y, z1.y, a);
                a = fmaf(h[j][1].z, z1.z, a);
                a = fmaf(h[j][1].w, z1.w, a);
                acc[bi][j] = a;
            }
        }
    }

    #pragma unroll
    for (int bi = 0; bi < 16; bi++)
        *(float4*)&g_dw[(size_t)bi*NTOT + n0] =
            make_float4(acc[bi][0], acc[bi][1], acc[bi][2], acc[bi][3]);
}

// ---------------------------------------------------------------------------
// Kernel B: standardize + build weights, emit fp16 hi/lo, [b][oc][tap][cin]
// ---------------------------------------------------------------------------
__global__ void __launch_bounds__(128) build_w(const float* __restrict__ base)
{
    const int b  = blockIdx.x >> 8;
    const int oc = blockIdx.x & 255;
    const int tid = threadIdx.x;

    const float* dwp = &g_dw[(size_t)b*NTOT + oc*FANIN];

    float v[9];
    float s = 0.f, sq = 0.f;
    #pragma unroll
    for (int t = 0; t < 9; t++) {
        v[t] = dwp[tid + t*128];
        s  += v[t];
        sq += v[t]*v[t];
    }
    #pragma unroll
    for (int off = 16; off; off >>= 1) {
        s  += __shfl_xor_sync(0xffffffffu, s,  off);
        sq += __shfl_xor_sync(0xffffffffu, sq, off);
    }
    __shared__ float ss[4], ssq[4];
    const int wid = tid >> 5;
    if ((tid & 31) == 0) { ss[wid] = s; ssq[wid] = sq; }
    __syncthreads();
    s  = ss[0] + ss[1] + ss[2] + ss[3];
    sq = ssq[0] + ssq[1] + ssq[2] + ssq[3];

    const float inv_n = 1.0f / (float)FANIN;
    float mu  = s * inv_n;
    float var = sq * inv_n - mu*mu;
    float rs  = rsqrtf(var + 1e-5f);
    const float inv_sqrt2 = 0.70710678118654752440f;
    float c1 = rs * sqrtf(2.0f / (float)FANIN) * inv_sqrt2;

    const float* bw = &base[(size_t)oc*FANIN];
    __half* whi = &g_whi[(size_t)(b*OC + oc)*9*IC];
    __half* wlo = &g_wlo[(size_t)(b*OC + oc)*9*IC];
    #pragma unroll
    for (int t = 0; t < 9; t++) {
        int i = tid + t*128;           // i = cin*9 + tap
        int cin = i / 9, tap = i - cin*9;
        float w = bw[i]*inv_sqrt2 + (v[t] - mu)*c1;
        __half hi = __float2half(w);
        __half lo = __float2half(w - __half2float(hi));
        whi[tap*IC + cin] = hi;
        wlo[tap*IC + cin] = lo;
    }
}

// ---------------------------------------------------------------------------
// Kernel C: implicit-GEMM conv via mma.sync fp16, 2-pass (w hi/lo, x single).
// CTA = (4 y-rows, 128-oc tile, b). 512 threads = 16 warps, warp tile 32oc x 64n.
// A tiles double-buffered: LDG(tap+1) overlaps compute(tap); 1 barrier/tap.
// ---------------------------------------------------------------------------
#define XS_STRIDE 144                  // bytes per (y,x) row of 64 cin fp16 (+16B pad)
#define XS_BYTES  (6*66*XS_STRIDE)     // 57024
#define A_BUF     36864                // one buffer: hi 18432 + lo 18432
#define SM_XS     73728                // after 2 A buffers
#define CONV_SMEM (SM_XS + XS_BYTES)   // 130752

__global__ void __launch_bounds__(512, 1) conv_mma(const float* __restrict__ x,
                                                   float* __restrict__ out)
{
    extern __shared__ char smem[];
    const int tid  = threadIdx.x;
    const int wid  = tid >> 5;
    const int lane = tid & 31;
    const int y0   = blockIdx.x * 4;
    const int oc0  = blockIdx.y * 128;
    const int b    = blockIdx.z;

    const int mw = wid & 3;       // oc quarter (32)
    const int yl = wid >> 2;      // local y row
    const int qr = lane >> 2;     // 0..7
    const int qc = lane & 3;      // 0..3

    float acc[2][8][4];
    #pragma unroll
    for (int mf = 0; mf < 2; mf++)
        #pragma unroll
        for (int nf = 0; nf < 8; nf++)
            #pragma unroll
            for (int q = 0; q < 4; q++) acc[mf][nf][q] = 0.f;

    uint4 nvh[2], nvl[2];   // in-flight A tile (hi/lo), 2 chunks per thread

    // ---- helpers ----
    auto lda = [&](int it) {
        const int ch = it / 9, tap = it - ch*9;
        const size_t abase = ((size_t)((b*OC + oc0)*9 + tap))*IC + (size_t)ch*64;
        #pragma unroll
        for (int u = 0; u < 2; u++) {
            const int i = tid + u*512;
            const int row = i >> 3, j = i & 7;
            const size_t off8 = (abase + (size_t)row*(9*IC)) / 8 + j;   // uint4 idx
            nvh[u] = ((const uint4*)g_whi)[off8];
            nvl[u] = ((const uint4*)g_wlo)[off8];
        }
    };
    auto sta = [&](int buf) {
        char* base = smem + buf*A_BUF;
        #pragma unroll
        for (int u = 0; u < 2; u++) {
            const int i = tid + u*512;
            const int row = i >> 3, j = i & 7;
            *(uint4*)(base +         row*XS_STRIDE + j*16) = nvh[u];
            *(uint4*)(base + 18432 + row*XS_STRIDE + j*16) = nvl[u];
        }
    };
    auto stage_x = [&](int ch) {
        for (int i = tid; i < 6*32*16; i += 512) {
            const int ys  = i >> 9;
            const int rem = i & 511;
            const int cp  = rem >> 4;      // c-pair 0..31
            const int x4  = rem & 15;
            const int gy  = y0 - 1 + ys;
            if (gy >= 0 && gy < HW) {
                const float4 v0 = *(const float4*)
                    &x[(((size_t)(b*IC + ch*64 + cp*2    ))*HW + gy)*HW + x4*4];
                const float4 v1 = *(const float4*)
                    &x[(((size_t)(b*IC + ch*64 + cp*2 + 1))*HW + gy)*HW + x4*4];
                const float f0[4] = {v0.x, v0.y, v0.z, v0.w};
                const float f1[4] = {v1.x, v1.y, v1.z, v1.w};
                #pragma unroll
                for (int q = 0; q < 4; q++) {
                    __half2 h = __floats2half2_rn(f0[q], f1[q]);
                    *(__half2*)(smem + SM_XS + (ys*66 + x4*4 + q + 1)*XS_STRIDE + cp*4) = h;
                }
            }
        }
    };
    auto compute = [&](int tap, int buf) {
        const int r = tap / 3, s = tap - r*3;
        const char* Ah = smem + buf*A_BUF;
        const char* Al = Ah + 18432;
        const int a_row0 = (mw*32 + qr)*XS_STRIDE + qc*4;
        const int bbase  = ((yl + r)*66 + s + qr)*XS_STRIDE + qc*4;
        #pragma unroll
        for (int ks = 0; ks < 4; ks++) {
            const int kb = ks*32;
            uint32_t ah[2][4], al[2][4];
            #pragma unroll
            for (int mf = 0; mf < 2; mf++) {
                const int ar = a_row0 + mf*(16*XS_STRIDE) + kb;
                ah[mf][0] = *(const uint32_t*)(Ah + ar);
                ah[mf][1] = *(const uint32_t*)(Ah + ar + 8*XS_STRIDE);
                ah[mf][2] = *(const uint32_t*)(Ah + ar + 16);
                ah[mf][3] = *(const uint32_t*)(Ah + ar + 8*XS_STRIDE + 16);
                al[mf][0] = *(const uint32_t*)(Al + ar);
                al[mf][1] = *(const uint32_t*)(Al + ar + 8*XS_STRIDE);
                al[mf][2] = *(const uint32_t*)(Al + ar + 16);
                al[mf][3] = *(const uint32_t*)(Al + ar + 8*XS_STRIDE + 16);
            }
            #pragma unroll
            for (int nf = 0; nf < 8; nf++) {
                const int ba = bbase + nf*(8*XS_STRIDE) + kb;
                const uint32_t b0 = *(const uint32_t*)(smem + SM_XS + ba);
                const uint32_t b1 = *(const uint32_t*)(smem + SM_XS + ba + 16);
                #pragma unroll
                for (int mf = 0; mf < 2; mf++) {
                    mma16816h(acc[mf][nf], ah[mf], b0, b1);
                    mma16816h(acc[mf][nf], al[mf], b0, b1);
                }
            }
        }
    };

    // ---- prologue: zero xs (halo/OOB stay zero), stage ch0 + A(0) ----
    for (int i = tid; i < XS_BYTES/16; i += 512)
        *(uint4*)(smem + SM_XS + i*16) = make_uint4(0u,0u,0u,0u);
    __syncthreads();
    stage_x(0);
    lda(0); sta(0);
    __syncthreads();

    // ---- main loop over (ch, tap) = 18 units, A double-buffered ----
    for (int it = 0; it < 18; it++) {
        const int tap = (it < 9) ? it : it - 9;
        const int buf = it & 1;
        if (it < 17) lda(it + 1);
        compute(tap, buf);
        if (it == 8) {
            __syncthreads();          // all warps done reading xs(ch0)
            stage_x(1);
            sta(buf ^ 1);
            __syncthreads();
        } else if (it < 17) {
            sta(buf ^ 1);
            __syncthreads();
        }
    }

    // ---- epilogue: d-frag -> gmem (float2 stores) ----
    const int y = y0 + yl;
    #pragma unroll
    for (int mf = 0; mf < 2; mf++) {
        const int oc = oc0 + mw*32 + mf*16 + qr;
        float* op0 = out + (((size_t)(b*OC + oc    )*HW) + y)*HW;
        float* op1 = out + (((size_t)(b*OC + oc + 8)*HW) + y)*HW;
        #pragma unroll
        for (int nf = 0; nf < 8; nf++) {
            const int xp = nf*8 + qc*2;
            *(float2*)&op0[xp] = make_float2(acc[mf][nf][0], acc[mf][nf][1]);
            *(float2*)&op1[xp] = make_float2(acc[mf][nf][2], acc[mf][nf][3]);
        }
    }
}

// ---------------------------------------------------------------------------
extern "C" void kernel_launch(void* const* d_in, const int* in_sizes, int n_in,
                              void* d_out, int out_size)
{
    const float* x    = (const float*)d_in[0];  // [16,128,64,64]
    const float* z    = (const float*)d_in[1];  // [16,256]
    const float* bw   = (const float*)d_in[2];  // [256,128,3,3]
    const float* hw   = (const float*)d_in[3];  // [294912,256]
    float*       out  = (float*)d_out;          // [16,256,64,64]

    static bool attr_set = false;
    if (!attr_set) {
        cudaFuncSetAttribute(conv_mma, cudaFuncAttributeMaxDynamicSharedMemorySize, CONV_SMEM);
        attr_set = true;
    }

    gemm_delta<<<NTOT/1024, 256>>>(z, hw);
    build_w<<<BATCH*OC, 128>>>(bw);
    conv_mma<<<dim3(16, 2, BATCH), 512, CONV_SMEM>>>(x, out);
}

// round 6
// speedup vs baseline: 2.2432x; 1.2778x over previous
#include <cuda_runtime.h>
#include <cuda_fp16.h>
#include <cstdint>
#include <math.h>

#define BATCH 16
#define ZD 256
#define OC 256
#define IC 128
#define FANIN (IC*9)          // 1152
#define NTOT (OC*FANIN)       // 294912
#define HW 64

// ---------------- device scratch (no allocation APIs) ----------------
__device__ float g_dw[BATCH*NTOT];             // delta_w [b][n]
__device__ __half g_wh[BATCH*OC*9*IC];         // weights fp16, [b][oc][tap][cin]

// fp16 mma.sync (sm_80-era PTX — valid on plain compute_103 virtual arch)
__device__ __forceinline__ void mma16816h(float* d, const uint32_t* a,
                                          uint32_t b0, uint32_t b1) {
    asm volatile(
        "mma.sync.aligned.m16n8k16.row.col.f32.f16.f16.f32 "
        "{%0,%1,%2,%3}, {%4,%5,%6,%7}, {%8,%9}, {%0,%1,%2,%3};"
        : "+f"(d[0]), "+f"(d[1]), "+f"(d[2]), "+f"(d[3])
        : "r"(a[0]), "r"(a[1]), "r"(a[2]), "r"(a[3]), "r"(b0), "r"(b1));
}

// ---------------------------------------------------------------------------
// Kernel A: delta[b][n] = sum_k z[b][k] * head_w[n][k]
// 2 n/thread -> 576 CTAs (was 288, grid-limited at 1.94/SM).
// ---------------------------------------------------------------------------
__global__ void __launch_bounds__(256, 4) gemm_delta(const float* __restrict__ z,
                                                     const float* __restrict__ hw)
{
    __shared__ float z_s[BATCH][ZD];   // 16 KB
    const int tid = threadIdx.x;

    {
        const float4* zg = (const float4*)z;
        float4* zs = (float4*)&z_s[0][0];
        #pragma unroll
        for (int f = tid; f < BATCH*ZD/4; f += 256) zs[f] = zg[f];
    }
    __syncthreads();

    const int n0 = blockIdx.x * 512 + tid * 2;

    float acc[16][2];
    #pragma unroll
    for (int bi = 0; bi < 16; bi++) { acc[bi][0] = 0.f; acc[bi][1] = 0.f; }

    for (int k = 0; k < ZD; k += 8) {
        float4 h[2][2];
        #pragma unroll
        for (int j = 0; j < 2; j++) {
            h[j][0] = *(const float4*)&hw[(size_t)(n0 + j)*ZD + k];
            h[j][1] = *(const float4*)&hw[(size_t)(n0 + j)*ZD + k + 4];
        }
        #pragma unroll
        for (int bi = 0; bi < 16; bi++) {
            float4 z0 = *(const float4*)&z_s[bi][k];
            float4 z1 = *(const float4*)&z_s[bi][k + 4];
            #pragma unroll
            for (int j = 0; j < 2; j++) {
                float a = acc[bi][j];
                a = fmaf(h[j][0].x, z0.x, a);
                a = fmaf(h[j][0].y, z0.y, a);
                a = fmaf(h[j][0].z, z0.z, a);
                a = fmaf(h[j][0].w, z0.w, a);
                a = fmaf(h[j][1].x, z1.x, a);
                a = fmaf(h[j][1].y, z1.y, a);
                a = fmaf(h[j][1].z, z1.z, a);
                a = fmaf(h[j][1].w, z1.w, a);
                acc[bi][j] = a;
            }
        }
    }

    #pragma unroll
    for (int bi = 0; bi < 16; bi++)
        *(float2*)&g_dw[(size_t)bi*NTOT + n0] = make_float2(acc[bi][0], acc[bi][1]);
}

// ---------------------------------------------------------------------------
// Kernel B: standardize + build weights, emit fp16, [b][oc][tap][cin]
// ---------------------------------------------------------------------------
__global__ void __launch_bounds__(128) build_w(const float* __restrict__ base)
{
    const int b  = blockIdx.x >> 8;
    const int oc = blockIdx.x & 255;
    const int tid = threadIdx.x;

    const float* dwp = &g_dw[(size_t)b*NTOT + oc*FANIN];

    float v[9];
    float s = 0.f, sq = 0.f;
    #pragma unroll
    for (int t = 0; t < 9; t++) {
        v[t] = dwp[tid + t*128];
        s  += v[t];
        sq += v[t]*v[t];
    }
    #pragma unroll
    for (int off = 16; off; off >>= 1) {
        s  += __shfl_xor_sync(0xffffffffu, s,  off);
        sq += __shfl_xor_sync(0xffffffffu, sq, off);
    }
    __shared__ float ss[4], ssq[4];
    const int wid = tid >> 5;
    if ((tid & 31) == 0) { ss[wid] = s; ssq[wid] = sq; }
    __syncthreads();
    s  = ss[0] + ss[1] + ss[2] + ss[3];
    sq = ssq[0] + ssq[1] + ssq[2] + ssq[3];

    const float inv_n = 1.0f / (float)FANIN;
    float mu  = s * inv_n;
    float var = sq * inv_n - mu*mu;
    float rs  = rsqrtf(var + 1e-5f);
    const float inv_sqrt2 = 0.70710678118654752440f;
    float c1 = rs * sqrtf(2.0f / (float)FANIN) * inv_sqrt2;

    const float* bw = &base[(size_t)oc*FANIN];
    __half* wh = &g_wh[(size_t)(b*OC + oc)*9*IC];
    #pragma unroll
    for (int t = 0; t < 9; t++) {
        int i = tid + t*128;           // i = cin*9 + tap
        int cin = i / 9, tap = i - cin*9;
        float w = bw[i]*inv_sqrt2 + (v[t] - mu)*c1;
        wh[tap*IC + cin] = __float2half(w);
    }
}

// ---------------------------------------------------------------------------
// Kernel C: implicit-GEMM conv via mma.sync fp16 single-pass, fp32 accum.
// CTA = (4 y-rows, 128-oc tile, b). 512 threads = 16 warps, warp tile 32oc x 64n.
// A tiles double-buffered: LDG(tap+1) overlaps compute(tap); 1 barrier/tap.
// ---------------------------------------------------------------------------
#define XS_STRIDE 144                  // bytes per (y,x) row of 64 cin fp16 (+16B pad)
#define XS_BYTES  (6*66*XS_STRIDE)     // 57024
#define A_BUF     18432                // one A buffer: 128 oc x 144B
#define SM_XS     36864                // after 2 A buffers
#define CONV_SMEM (SM_XS + XS_BYTES)   // 93888

__global__ void __launch_bounds__(512, 1) conv_mma(const float* __restrict__ x,
                                                   float* __restrict__ out)
{
    extern __shared__ char smem[];
    const int tid  = threadIdx.x;
    const int wid  = tid >> 5;
    const int lane = tid & 31;
    const int y0   = blockIdx.x * 4;
    const int oc0  = blockIdx.y * 128;
    const int b    = blockIdx.z;

    const int mw = wid & 3;       // oc quarter (32)
    const int yl = wid >> 2;      // local y row
    const int qr = lane >> 2;     // 0..7
    const int qc = lane & 3;      // 0..3

    float acc[2][8][4];
    #pragma unroll
    for (int mf = 0; mf < 2; mf++)
        #pragma unroll
        for (int nf = 0; nf < 8; nf++)
            #pragma unroll
            for (int q = 0; q < 4; q++) acc[mf][nf][q] = 0.f;

    uint4 nv[2];   // in-flight A tile, 2 chunks per thread

    // ---- helpers ----
    auto lda = [&](int it) {
        const int ch = it / 9, tap = it - ch*9;
        const size_t abase = ((size_t)((b*OC + oc0)*9 + tap))*IC + (size_t)ch*64;
        #pragma unroll
        for (int u = 0; u < 2; u++) {
            const int i = tid + u*512;
            const int row = i >> 3, j = i & 7;
            const size_t off8 = (abase + (size_t)row*(9*IC)) / 8 + j;   // uint4 idx
            nv[u] = ((const uint4*)g_wh)[off8];
        }
    };
    auto sta = [&](int buf) {
        char* base = smem + buf*A_BUF;
        #pragma unroll
        for (int u = 0; u < 2; u++) {
            const int i = tid + u*512;
            const int row = i >> 3, j = i & 7;
            *(uint4*)(base + row*XS_STRIDE + j*16) = nv[u];
        }
    };
    auto stage_x = [&](int ch) {
        for (int i = tid; i < 6*32*16; i += 512) {
            const int ys  = i >> 9;
            const int rem = i & 511;
            const int cp  = rem >> 4;      // c-pair 0..31
            const int x4  = rem & 15;
            const int gy  = y0 - 1 + ys;
            if (gy >= 0 && gy < HW) {
                const float4 v0 = *(const float4*)
                    &x[(((size_t)(b*IC + ch*64 + cp*2    ))*HW + gy)*HW + x4*4];
                const float4 v1 = *(const float4*)
                    &x[(((size_t)(b*IC + ch*64 + cp*2 + 1))*HW + gy)*HW + x4*4];
                const float f0[4] = {v0.x, v0.y, v0.z, v0.w};
                const float f1[4] = {v1.x, v1.y, v1.z, v1.w};
                #pragma unroll
                for (int q = 0; q < 4; q++) {
                    __half2 h = __floats2half2_rn(f0[q], f1[q]);
                    *(__half2*)(smem + SM_XS + (ys*66 + x4*4 + q + 1)*XS_STRIDE + cp*4) = h;
                }
            }
        }
    };
    auto compute = [&](int tap, int buf) {
        const int r = tap / 3, s = tap - r*3;
        const char* Ah = smem + buf*A_BUF;
        const int a_row0 = (mw*32 + qr)*XS_STRIDE + qc*4;
        const int bbase  = ((yl + r)*66 + s + qr)*XS_STRIDE + qc*4;
        #pragma unroll
        for (int ks = 0; ks < 4; ks++) {
            const int kb = ks*32;
            uint32_t ah[2][4];
            #pragma unroll
            for (int mf = 0; mf < 2; mf++) {
                const int ar = a_row0 + mf*(16*XS_STRIDE) + kb;
                ah[mf][0] = *(const uint32_t*)(Ah + ar);
                ah[mf][1] = *(const uint32_t*)(Ah + ar + 8*XS_STRIDE);
                ah[mf][2] = *(const uint32_t*)(Ah + ar + 16);
                ah[mf][3] = *(const uint32_t*)(Ah + ar + 8*XS_STRIDE + 16);
            }
            #pragma unroll
            for (int nf = 0; nf < 8; nf++) {
                const int ba = bbase + nf*(8*XS_STRIDE) + kb;
                const uint32_t b0 = *(const uint32_t*)(smem + SM_XS + ba);
                const uint32_t b1 = *(const uint32_t*)(smem + SM_XS + ba + 16);
                #pragma unroll
                for (int mf = 0; mf < 2; mf++)
                    mma16816h(acc[mf][nf], ah[mf], b0, b1);
            }
        }
    };

    // ---- prologue: zero xs (halo/OOB stay zero), stage ch0 + A(0) ----
    for (int i = tid; i < XS_BYTES/16; i += 512)
        *(uint4*)(smem + SM_XS + i*16) = make_uint4(0u,0u,0u,0u);
    __syncthreads();
    stage_x(0);
    lda(0); sta(0);
    __syncthreads();

    // ---- main loop over (ch, tap) = 18 units, A double-buffered ----
    for (int it = 0; it < 18; it++) {
        const int tap = (it < 9) ? it : it - 9;
        const int buf = it & 1;
        if (it < 17) lda(it + 1);
        compute(tap, buf);
        if (it == 8) {
            __syncthreads();          // all warps done reading xs(ch0)
            stage_x(1);
            sta(buf ^ 1);
            __syncthreads();
        } else if (it < 17) {
            sta(buf ^ 1);
            __syncthreads();
        }
    }

    // ---- epilogue: d-frag -> gmem (float2 stores) ----
    const int y = y0 + yl;
    #pragma unroll
    for (int mf = 0; mf < 2; mf++) {
        const int oc = oc0 + mw*32 + mf*16 + qr;
        float* op0 = out + (((size_t)(b*OC + oc    )*HW) + y)*HW;
        float* op1 = out + (((size_t)(b*OC + oc + 8)*HW) + y)*HW;
        #pragma unroll
        for (int nf = 0; nf < 8; nf++) {
            const int xp = nf*8 + qc*2;
            *(float2*)&op0[xp] = make_float2(acc[mf][nf][0], acc[mf][nf][1]);
            *(float2*)&op1[xp] = make_float2(acc[mf][nf][2], acc[mf][nf][3]);
        }
    }
}

// ---------------------------------------------------------------------------
extern "C" void kernel_launch(void* const* d_in, const int* in_sizes, int n_in,
                              void* d_out, int out_size)
{
    const float* x    = (const float*)d_in[0];  // [16,128,64,64]
    const float* z    = (const float*)d_in[1];  // [16,256]
    const float* bw   = (const float*)d_in[2];  // [256,128,3,3]
    const float* hw   = (const float*)d_in[3];  // [294912,256]
    float*       out  = (float*)d_out;          // [16,256,64,64]

    static bool attr_set = false;
    if (!attr_set) {
        cudaFuncSetAttribute(conv_mma, cudaFuncAttributeMaxDynamicSharedMemorySize, CONV_SMEM);
        attr_set = true;
    }

    gemm_delta<<<NTOT/512, 256>>>(z, hw);
    build_w<<<BATCH*OC, 128>>>(bw);
    conv_mma<<<dim3(16, 2, BATCH), 512, CONV_SMEM>>>(x, out);
}

// round 7
// speedup vs baseline: 2.4081x; 1.0735x over previous
#include <cuda_runtime.h>
#include <cuda_fp16.h>
#include <cstdint>
#include <math.h>

#define BATCH 16
#define ZD 256
#define OC 256
#define IC 128
#define FANIN (IC*9)          // 1152
#define NTOT (OC*FANIN)       // 294912
#define HW 64

// ---------------- device scratch (no allocation APIs) ----------------
__device__ float g_dw[BATCH*NTOT];             // delta_w [b][n]
__device__ __half g_wh[BATCH*OC*9*IC];         // weights fp16, [b][oc][tap][cin]

// fp16 mma.sync (sm_80-era PTX — valid on plain compute_103 virtual arch)
__device__ __forceinline__ void mma16816h(float* d, const uint32_t* a,
                                          uint32_t b0, uint32_t b1) {
    asm volatile(
        "mma.sync.aligned.m16n8k16.row.col.f32.f16.f16.f32 "
        "{%0,%1,%2,%3}, {%4,%5,%6,%7}, {%8,%9}, {%0,%1,%2,%3};"
        : "+f"(d[0]), "+f"(d[1]), "+f"(d[2]), "+f"(d[3])
        : "r"(a[0]), "r"(a[1]), "r"(a[2]), "r"(a[3]), "r"(b0), "r"(b1));
}

__device__ __forceinline__ uint32_t pack_h2(float a, float b) {
    __half2 h = __floats2half2_rn(a, b);
    return *reinterpret_cast<uint32_t*>(&h);
}

// k-pair permutation within each 32B (k16) group:
// pair p (k = 2p,2p+1; p 0..7) stored at position pos(p) = 2(p&3) | (p>>2).
// Read side: LDS.64 at byte 8*qc returns positions 2qc,2qc+1 = pairs (qc, qc+4)
// = exactly (b0, b1) / (a0, a2) of mma.m16n8k16.
__device__ __forceinline__ int kperm_pos(int lp) { return ((lp & 3) << 1) | (lp >> 2); }

// ---------------------------------------------------------------------------
// Kernel A: delta[b][n] = sum_k z[b][k] * head_w[n][k]  via HMMA.
// Block: 64-n tile, full K=256, all 16 batches. 256 threads = 8 warps,
// warp handles one n8 strip over full K. DRAM-bound by head_w stream.
// ---------------------------------------------------------------------------
#define HWS_STRIDE 528     // 256 k * 2B + 16B pad

__global__ void __launch_bounds__(256) gemm_hmma(const float* __restrict__ z,
                                                 const float* __restrict__ hw)
{
    __shared__ uint4 zf[512];            // A-frags: [kk(16)][lane(32)] x 16B
    __shared__ char  hws[64*HWS_STRIDE]; // B fp16, k-pair permuted

    const int tid = threadIdx.x;
    const int n0  = blockIdx.x * 64;

    // ---- build z A-fragments (16 kk x 32 lanes) ----
    #pragma unroll
    for (int u = 0; u < 2; u++) {
        const int s  = tid + u*256;
        const int kk = s >> 5, l = s & 31;
        const int m  = l >> 2;
        const int kb = kk*16 + 2*(l & 3);
        float2 f0 = *(const float2*)&z[m*ZD + kb];
        float2 f1 = *(const float2*)&z[(m+8)*ZD + kb];
        float2 f2 = *(const float2*)&z[m*ZD + kb + 8];
        float2 f3 = *(const float2*)&z[(m+8)*ZD + kb + 8];
        uint4 v;
        v.x = pack_h2(f0.x, f0.y);
        v.y = pack_h2(f1.x, f1.y);
        v.z = pack_h2(f2.x, f2.y);
        v.w = pack_h2(f3.x, f3.y);
        zf[s] = v;
    }

    // ---- stage head_w tile: 64 rows x 256 k, fp32 -> fp16, permuted ----
    #pragma unroll
    for (int half = 0; half < 2; half++) {
        float4 vals[8];
        #pragma unroll
        for (int u = 0; u < 8; u++) {
            const int idx = (half*8 + u)*256 + tid;
            const int row = idx >> 6, kq = idx & 63;
            vals[u] = *(const float4*)&hw[(size_t)(n0 + row)*ZD + kq*4];
        }
        #pragma unroll
        for (int u = 0; u < 8; u++) {
            const int idx = (half*8 + u)*256 + tid;
            const int row = idx >> 6, kq = idx & 63;
            const int g   = kq >> 2;
            const int lp0 = 2*(kq & 3);
            char* rp = hws + row*HWS_STRIDE + g*32;
            *(uint32_t*)(rp + kperm_pos(lp0)*4)     = pack_h2(vals[u].x, vals[u].y);
            *(uint32_t*)(rp + kperm_pos(lp0 + 1)*4) = pack_h2(vals[u].z, vals[u].w);
        }
    }
    __syncthreads();

    // ---- compute: warp w -> n rows w*8..w*8+7, K=256 ----
    const int wid = tid >> 5, lane = tid & 31;
    const int qr = lane >> 2, qc = lane & 3;

    float d[4] = {0.f, 0.f, 0.f, 0.f};
    const char* bp = hws + (wid*8 + qr)*HWS_STRIDE + qc*8;
    #pragma unroll
    for (int kk = 0; kk < 16; kk++) {
        uint4 a = zf[kk*32 + lane];
        uint2 b = *(const uint2*)(bp + kk*32);
        mma16816h(d, (const uint32_t*)&a, b.x, b.y);
    }

    const int n = n0 + wid*8 + 2*qc;
    *(float2*)&g_dw[(size_t)qr*NTOT + n]       = make_float2(d[0], d[1]);
    *(float2*)&g_dw[(size_t)(qr + 8)*NTOT + n] = make_float2(d[2], d[3]);
}

// ---------------------------------------------------------------------------
// Kernel B: standardize + build weights, emit fp16, [b][oc][tap][cin]
// ---------------------------------------------------------------------------
__global__ void __launch_bounds__(128) build_w(const float* __restrict__ base)
{
    const int b  = blockIdx.x >> 8;
    const int oc = blockIdx.x & 255;
    const int tid = threadIdx.x;

    const float* dwp = &g_dw[(size_t)b*NTOT + oc*FANIN];

    float v[9];
    float s = 0.f, sq = 0.f;
    #pragma unroll
    for (int t = 0; t < 9; t++) {
        v[t] = dwp[tid + t*128];
        s  += v[t];
        sq += v[t]*v[t];
    }
    #pragma unroll
    for (int off = 16; off; off >>= 1) {
        s  += __shfl_xor_sync(0xffffffffu, s,  off);
        sq += __shfl_xor_sync(0xffffffffu, sq, off);
    }
    __shared__ float ss[4], ssq[4];
    const int wid = tid >> 5;
    if ((tid & 31) == 0) { ss[wid] = s; ssq[wid] = sq; }
    __syncthreads();
    s  = ss[0] + ss[1] + ss[2] + ss[3];
    sq = ssq[0] + ssq[1] + ssq[2] + ssq[3];

    const float inv_n = 1.0f / (float)FANIN;
    float mu  = s * inv_n;
    float var = sq * inv_n - mu*mu;
    float rs  = rsqrtf(var + 1e-5f);
    const float inv_sqrt2 = 0.70710678118654752440f;
    float c1 = rs * sqrtf(2.0f / (float)FANIN) * inv_sqrt2;

    const float* bw = &base[(size_t)oc*FANIN];
    __half* wh = &g_wh[(size_t)(b*OC + oc)*9*IC];
    #pragma unroll
    for (int t = 0; t < 9; t++) {
        int i = tid + t*128;           // i = cin*9 + tap
        int cin = i / 9, tap = i - cin*9;
        float w = bw[i]*inv_sqrt2 + (v[t] - mu)*c1;
        wh[tap*IC + cin] = __float2half(w);
    }
}

// ---------------------------------------------------------------------------
// Kernel C: implicit-GEMM conv via mma.sync fp16 single-pass, fp32 accum.
// CTA = (4 y-rows, 128-oc tile, b). 512 threads = 16 warps, warp tile 32oc x 64n.
// A double-buffered; k-pair permuted smem so all frag loads are LDS.64.
// ---------------------------------------------------------------------------
#define XS_STRIDE 144                  // bytes per (y,x) row of 64 cin fp16 (+16B pad)
#define XS_BYTES  (6*66*XS_STRIDE)     // 57024
#define A_BUF     18432                // one A buffer: 128 oc x 144B
#define SM_XS     36864                // after 2 A buffers
#define CONV_SMEM (SM_XS + XS_BYTES)   // 93888

__global__ void __launch_bounds__(512, 1) conv_mma(const float* __restrict__ x,
                                                   float* __restrict__ out)
{
    extern __shared__ char smem[];
    const int tid  = threadIdx.x;
    const int wid  = tid >> 5;
    const int lane = tid & 31;
    const int y0   = blockIdx.x * 4;
    const int oc0  = blockIdx.y * 128;
    const int b    = blockIdx.z;

    const int mw = wid & 3;       // oc quarter (32)
    const int yl = wid >> 2;      // local y row
    const int qr = lane >> 2;     // 0..7
    const int qc = lane & 3;      // 0..3

    float acc[2][8][4];
    #pragma unroll
    for (int mf = 0; mf < 2; mf++)
        #pragma unroll
        for (int nf = 0; nf < 8; nf++)
            #pragma unroll
            for (int q = 0; q < 4; q++) acc[mf][nf][q] = 0.f;

    uint4 nv[2];   // in-flight A tile, 2 chunks per thread

    // ---- helpers ----
    auto lda = [&](int it) {
        const int ch = it / 9, tap = it - ch*9;
        const size_t abase = ((size_t)((b*OC + oc0)*9 + tap))*IC + (size_t)ch*64;
        #pragma unroll
        for (int u = 0; u < 2; u++) {
            const int i = tid + u*512;
            const int row = i >> 3, j = i & 7;
            const size_t off8 = (abase + (size_t)row*(9*IC)) / 8 + j;   // uint4 idx
            nv[u] = ((const uint4*)g_wh)[off8];
        }
    };
    auto sta = [&](int buf) {
        char* base = smem + buf*A_BUF;
        #pragma unroll
        for (int u = 0; u < 2; u++) {
            const int i = tid + u*512;
            const int row = i >> 3, j = i & 7;
            // uint4 = cin pairs 4j..4j+3; group g=j>>1, local pairs (j&1)*4 + q
            char* p = base + row*XS_STRIDE + (j >> 1)*32 + (j & 1)*4;
            *(uint32_t*)(p)      = nv[u].x;
            *(uint32_t*)(p + 8)  = nv[u].y;
            *(uint32_t*)(p + 16) = nv[u].z;
            *(uint32_t*)(p + 24) = nv[u].w;
        }
    };
    auto stage_x = [&](int ch) {
        for (int i = tid; i < 6*32*16; i += 512) {
            const int ys  = i >> 9;
            const int rem = i & 511;
            const int cp  = rem >> 4;      // c-pair 0..31
            const int x4  = rem & 15;
            const int gy  = y0 - 1 + ys;
            const int off_k = (cp >> 3)*32 + kperm_pos(cp & 7)*4;
            if (gy >= 0 && gy < HW) {
                const float4 v0 = *(const float4*)
                    &x[(((size_t)(b*IC + ch*64 + cp*2    ))*HW + gy)*HW + x4*4];
                const float4 v1 = *(const float4*)
                    &x[(((size_t)(b*IC + ch*64 + cp*2 + 1))*HW + gy)*HW + x4*4];
                const float f0[4] = {v0.x, v0.y, v0.z, v0.w};
                const float f1[4] = {v1.x, v1.y, v1.z, v1.w};
                #pragma unroll
                for (int q = 0; q < 4; q++) {
                    uint32_t h = pack_h2(f0[q], f1[q]);
                    *(uint32_t*)(smem + SM_XS + (ys*66 + x4*4 + q + 1)*XS_STRIDE + off_k) = h;
                }
            }
        }
    };
    auto compute = [&](int tap, int buf) {
        const int r = tap / 3, s = tap - r*3;
        const char* Ah = smem + buf*A_BUF;
        const int a_row0 = (mw*32 + qr)*XS_STRIDE + qc*8;
        const int bbase  = ((yl + r)*66 + s + qr)*XS_STRIDE + qc*8;
        #pragma unroll
        for (int ks = 0; ks < 4; ks++) {
            const int kb = ks*32;
            uint32_t ah[2][4];
            #pragma unroll
            for (int mf = 0; mf < 2; mf++) {
                const int ar = a_row0 + mf*(16*XS_STRIDE) + kb;
                uint2 a02 = *(const uint2*)(Ah + ar);
                uint2 a13 = *(const uint2*)(Ah + ar + 8*XS_STRIDE);
                ah[mf][0] = a02.x; ah[mf][1] = a13.x;
                ah[mf][2] = a02.y; ah[mf][3] = a13.y;
            }
            #pragma unroll
            for (int nf = 0; nf < 8; nf++) {
                const uint2 bv = *(const uint2*)(smem + SM_XS + bbase + nf*(8*XS_STRIDE) + kb);
                #pragma unroll
                for (int mf = 0; mf < 2; mf++)
                    mma16816h(acc[mf][nf], ah[mf], bv.x, bv.y);
            }
        }
    };

    // ---- prologue: zero xs (halo/OOB stay zero), stage ch0 + A(0) ----
    for (int i = tid; i < XS_BYTES/16; i += 512)
        *(uint4*)(smem + SM_XS + i*16) = make_uint4(0u,0u,0u,0u);
    __syncthreads();
    stage_x(0);
    lda(0); sta(0);
    __syncthreads();

    // ---- main loop over (ch, tap) = 18 units, A double-buffered ----
    for (int it = 0; it < 18; it++) {
        const int tap = (it < 9) ? it : it - 9;
        const int buf = it & 1;
        if (it < 17) lda(it + 1);
        compute(tap, buf);
        if (it == 8) {
            __syncthreads();          // all warps done reading xs(ch0)
            stage_x(1);
            sta(buf ^ 1);
            __syncthreads();
        } else if (it < 17) {
            sta(buf ^ 1);
            __syncthreads();
        }
    }

    // ---- epilogue: d-frag -> gmem (float2 stores) ----
    const int y = y0 + yl;
    #pragma unroll
    for (int mf = 0; mf < 2; mf++) {
        const int oc = oc0 + mw*32 + mf*16 + qr;
        float* op0 = out + (((size_t)(b*OC + oc    )*HW) + y)*HW;
        float* op1 = out + (((size_t)(b*OC + oc + 8)*HW) + y)*HW;
        #pragma unroll
        for (int nf = 0; nf < 8; nf++) {
            const int xp = nf*8 + qc*2;
            *(float2*)&op0[xp] = make_float2(acc[mf][nf][0], acc[mf][nf][1]);
            *(float2*)&op1[xp] = make_float2(acc[mf][nf][2], acc[mf][nf][3]);
        }
    }
}

// ---------------------------------------------------------------------------
extern "C" void kernel_launch(void* const* d_in, const int* in_sizes, int n_in,
                              void* d_out, int out_size)
{
    const float* x    = (const float*)d_in[0];  // [16,128,64,64]
    const float* z    = (const float*)d_in[1];  // [16,256]
    const float* bw   = (const float*)d_in[2];  // [256,128,3,3]
    const float* hw   = (const float*)d_in[3];  // [294912,256]
    float*       out  = (float*)d_out;          // [16,256,64,64]

    static bool attr_set = false;
    if (!attr_set) {
        cudaFuncSetAttribute(conv_mma, cudaFuncAttributeMaxDynamicSharedMemorySize, CONV_SMEM);
        attr_set = true;
    }

    gemm_hmma<<<NTOT/64, 256>>>(z, hw);
    build_w<<<BATCH*OC, 128>>>(bw);
    conv_mma<<<dim3(16, 2, BATCH), 512, CONV_SMEM>>>(x, out);
}

// round 8
// speedup vs baseline: 2.7664x; 1.1488x over previous
#include <cuda_runtime.h>
#include <cuda_fp16.h>
#include <cstdint>
#include <math.h>

#define BATCH 16
#define ZD 256
#define OC 256
#define IC 128
#define FANIN (IC*9)          // 1152
#define NTOT (OC*FANIN)       // 294912
#define HW 64

// ---------------- device scratch (no allocation APIs) ----------------
__device__ float g_dw[BATCH*NTOT];             // delta_w [b][n]
__device__ __half g_wh[BATCH*OC*9*IC];         // weights fp16, [b][oc][tap][cin]

// fp16 mma.sync (sm_80-era PTX — valid on plain compute_103 virtual arch)
__device__ __forceinline__ void mma16816h(float* d, const uint32_t* a,
                                          uint32_t b0, uint32_t b1) {
    asm volatile(
        "mma.sync.aligned.m16n8k16.row.col.f32.f16.f16.f32 "
        "{%0,%1,%2,%3}, {%4,%5,%6,%7}, {%8,%9}, {%0,%1,%2,%3};"
        : "+f"(d[0]), "+f"(d[1]), "+f"(d[2]), "+f"(d[3])
        : "r"(a[0]), "r"(a[1]), "r"(a[2]), "r"(a[3]), "r"(b0), "r"(b1));
}

__device__ __forceinline__ uint32_t pack_h2(float a, float b) {
    __half2 h = __floats2half2_rn(a, b);
    return *reinterpret_cast<uint32_t*>(&h);
}

// k-pair permutation (used by gemm_hmma only)
__device__ __forceinline__ int kperm_pos(int lp) { return ((lp & 3) << 1) | (lp >> 2); }

// ---------------------------------------------------------------------------
// Kernel A: delta[b][n] = sum_k z[b][k] * head_w[n][k]  via HMMA.
// Block: 64-n tile, full K=256, all 16 batches. 256 threads = 8 warps.
// DRAM-bound by the 302MB head_w stream (70% of spec measured).
// ---------------------------------------------------------------------------
#define HWS_STRIDE 528     // 256 k * 2B + 16B pad

__global__ void __launch_bounds__(256) gemm_hmma(const float* __restrict__ z,
                                                 const float* __restrict__ hw)
{
    __shared__ uint4 zf[512];            // A-frags: [kk(16)][lane(32)] x 16B
    __shared__ char  hws[64*HWS_STRIDE]; // B fp16, k-pair permuted

    const int tid = threadIdx.x;
    const int n0  = blockIdx.x * 64;

    // ---- build z A-fragments (16 kk x 32 lanes) ----
    #pragma unroll
    for (int u = 0; u < 2; u++) {
        const int s  = tid + u*256;
        const int kk = s >> 5, l = s & 31;
        const int m  = l >> 2;
        const int kb = kk*16 + 2*(l & 3);
        float2 f0 = *(const float2*)&z[m*ZD + kb];
        float2 f1 = *(const float2*)&z[(m+8)*ZD + kb];
        float2 f2 = *(const float2*)&z[m*ZD + kb + 8];
        float2 f3 = *(const float2*)&z[(m+8)*ZD + kb + 8];
        uint4 v;
        v.x = pack_h2(f0.x, f0.y);
        v.y = pack_h2(f1.x, f1.y);
        v.z = pack_h2(f2.x, f2.y);
        v.w = pack_h2(f3.x, f3.y);
        zf[s] = v;
    }

    // ---- stage head_w tile: 64 rows x 256 k, fp32 -> fp16, permuted ----
    #pragma unroll
    for (int half = 0; half < 2; half++) {
        float4 vals[8];
        #pragma unroll
        for (int u = 0; u < 8; u++) {
            const int idx = (half*8 + u)*256 + tid;
            const int row = idx >> 6, kq = idx & 63;
            vals[u] = *(const float4*)&hw[(size_t)(n0 + row)*ZD + kq*4];
        }
        #pragma unroll
        for (int u = 0; u < 8; u++) {
            const int idx = (half*8 + u)*256 + tid;
            const int row = idx >> 6, kq = idx & 63;
            const int g   = kq >> 2;
            const int lp0 = 2*(kq & 3);
            char* rp = hws + row*HWS_STRIDE + g*32;
            *(uint32_t*)(rp + kperm_pos(lp0)*4)     = pack_h2(vals[u].x, vals[u].y);
            *(uint32_t*)(rp + kperm_pos(lp0 + 1)*4) = pack_h2(vals[u].z, vals[u].w);
        }
    }
    __syncthreads();

    // ---- compute: warp w -> n rows w*8..w*8+7, K=256 ----
    const int wid = tid >> 5, lane = tid & 31;
    const int qr = lane >> 2, qc = lane & 3;

    float d[4] = {0.f, 0.f, 0.f, 0.f};
    const char* bp = hws + (wid*8 + qr)*HWS_STRIDE + qc*8;
    #pragma unroll
    for (int kk = 0; kk < 16; kk++) {
        uint4 a = zf[kk*32 + lane];
        uint2 b = *(const uint2*)(bp + kk*32);
        mma16816h(d, (const uint32_t*)&a, b.x, b.y);
    }

    const int n = n0 + wid*8 + 2*qc;
    *(float2*)&g_dw[(size_t)qr*NTOT + n]       = make_float2(d[0], d[1]);
    *(float2*)&g_dw[(size_t)(qr + 8)*NTOT + n] = make_float2(d[2], d[3]);
}

// ---------------------------------------------------------------------------
// Kernel B: standardize + build weights, emit fp16, [b][oc][tap][cin]
// ---------------------------------------------------------------------------
__global__ void __launch_bounds__(128) build_w(const float* __restrict__ base)
{
    const int b  = blockIdx.x >> 8;
    const int oc = blockIdx.x & 255;
    const int tid = threadIdx.x;

    const float* dwp = &g_dw[(size_t)b*NTOT + oc*FANIN];

    float v[9];
    float s = 0.f, sq = 0.f;
    #pragma unroll
    for (int t = 0; t < 9; t++) {
        v[t] = dwp[tid + t*128];
        s  += v[t];
        sq += v[t]*v[t];
    }
    #pragma unroll
    for (int off = 16; off; off >>= 1) {
        s  += __shfl_xor_sync(0xffffffffu, s,  off);
        sq += __shfl_xor_sync(0xffffffffu, sq, off);
    }
    __shared__ float ss[4], ssq[4];
    const int wid = tid >> 5;
    if ((tid & 31) == 0) { ss[wid] = s; ssq[wid] = sq; }
    __syncthreads();
    s  = ss[0] + ss[1] + ss[2] + ss[3];
    sq = ssq[0] + ssq[1] + ssq[2] + ssq[3];

    const float inv_n = 1.0f / (float)FANIN;
    float mu  = s * inv_n;
    float var = sq * inv_n - mu*mu;
    float rs  = rsqrtf(var + 1e-5f);
    const float inv_sqrt2 = 0.70710678118654752440f;
    float c1 = rs * sqrtf(2.0f / (float)FANIN) * inv_sqrt2;

    const float* bw = &base[(size_t)oc*FANIN];
    __half* wh = &g_wh[(size_t)(b*OC + oc)*9*IC];
    #pragma unroll
    for (int t = 0; t < 9; t++) {
        int i = tid + t*128;           // i = cin*9 + tap
        int cin = i / 9, tap = i - cin*9;
        float w = bw[i]*inv_sqrt2 + (v[t] - mu)*c1;
        wh[tap*IC + cin] = __float2half(w);
    }
}

// ---------------------------------------------------------------------------
// Kernel C: implicit-GEMM conv via mma.sync fp16 single-pass, fp32 accum.
// CTA = (4 y-rows, 128-oc tile, b). 512 threads = 16 warps, warp tile 32oc x 64n.
// R6 layout (LDS.32 fragment loads — measured at the HMMA-rate ceiling).
// ---------------------------------------------------------------------------
#define XS_STRIDE 144                  // bytes per (y,x) row of 64 cin fp16 (+16B pad)
#define XS_BYTES  (6*66*XS_STRIDE)     // 57024
#define A_BUF     18432                // one A buffer: 128 oc x 144B
#define SM_XS     36864                // after 2 A buffers
#define CONV_SMEM (SM_XS + XS_BYTES)   // 93888

__global__ void __launch_bounds__(512, 1) conv_mma(const float* __restrict__ x,
                                                   float* __restrict__ out)
{
    extern __shared__ char smem[];
    const int tid  = threadIdx.x;
    const int wid  = tid >> 5;
    const int lane = tid & 31;
    const int y0   = blockIdx.x * 4;
    const int oc0  = blockIdx.y * 128;
    const int b    = blockIdx.z;

    const int mw = wid & 3;       // oc quarter (32)
    const int yl = wid >> 2;      // local y row
    const int qr = lane >> 2;     // 0..7
    const int qc = lane & 3;      // 0..3

    float acc[2][8][4];
    #pragma unroll
    for (int mf = 0; mf < 2; mf++)
        #pragma unroll
        for (int nf = 0; nf < 8; nf++)
            #pragma unroll
            for (int q = 0; q < 4; q++) acc[mf][nf][q] = 0.f;

    uint4 nv[2];   // in-flight A tile, 2 chunks per thread

    // ---- helpers ----
    auto lda = [&](int it) {
        const int ch = it / 9, tap = it - ch*9;
        const size_t abase = ((size_t)((b*OC + oc0)*9 + tap))*IC + (size_t)ch*64;
        #pragma unroll
        for (int u = 0; u < 2; u++) {
            const int i = tid + u*512;
            const int row = i >> 3, j = i & 7;
            const size_t off8 = (abase + (size_t)row*(9*IC)) / 8 + j;   // uint4 idx
            nv[u] = ((const uint4*)g_wh)[off8];
        }
    };
    auto sta = [&](int buf) {
        char* base = smem + buf*A_BUF;
        #pragma unroll
        for (int u = 0; u < 2; u++) {
            const int i = tid + u*512;
            const int row = i >> 3, j = i & 7;
            *(uint4*)(base + row*XS_STRIDE + j*16) = nv[u];
        }
    };
    auto stage_x = [&](int ch) {
        for (int i = tid; i < 6*32*16; i += 512) {
            const int ys  = i >> 9;
            const int rem = i & 511;
            const int cp  = rem >> 4;      // c-pair 0..31
            const int x4  = rem & 15;
            const int gy  = y0 - 1 + ys;
            if (gy >= 0 && gy < HW) {
                const float4 v0 = *(const float4*)
                    &x[(((size_t)(b*IC + ch*64 + cp*2    ))*HW + gy)*HW + x4*4];
                const float4 v1 = *(const float4*)
                    &x[(((size_t)(b*IC + ch*64 + cp*2 + 1))*HW + gy)*HW + x4*4];
                const float f0[4] = {v0.x, v0.y, v0.z, v0.w};
                const float f1[4] = {v1.x, v1.y, v1.z, v1.w};
                #pragma unroll
                for (int q = 0; q < 4; q++) {
                    __half2 h = __floats2half2_rn(f0[q], f1[q]);
                    *(__half2*)(smem + SM_XS + (ys*66 + x4*4 + q + 1)*XS_STRIDE + cp*4) = h;
                }
            }
        }
    };
    auto compute = [&](int tap, int buf) {
        const int r = tap / 3, s = tap - r*3;
        const char* Ah = smem + buf*A_BUF;
        const int a_row0 = (mw*32 + qr)*XS_STRIDE + qc*4;
        const int bbase  = ((yl + r)*66 + s + qr)*XS_STRIDE + qc*4;
        #pragma unroll
        for (int ks = 0; ks < 4; ks++) {
            const int kb = ks*32;
            uint32_t ah[2][4];
            #pragma unroll
            for (int mf = 0; mf < 2; mf++) {
                const int ar = a_row0 + mf*(16*XS_STRIDE) + kb;
                ah[mf][0] = *(const uint32_t*)(Ah + ar);
                ah[mf][1] = *(const uint32_t*)(Ah + ar + 8*XS_STRIDE);
                ah[mf][2] = *(const uint32_t*)(Ah + ar + 16);
                ah[mf][3] = *(const uint32_t*)(Ah + ar + 8*XS_STRIDE + 16);
            }
            #pragma unroll
            for (int nf = 0; nf < 8; nf++) {
                const int ba = bbase + nf*(8*XS_STRIDE) + kb;
                const uint32_t b0 = *(const uint32_t*)(smem + SM_XS + ba);
                const uint32_t b1 = *(const uint32_t*)(smem + SM_XS + ba + 16);
                #pragma unroll
                for (int mf = 0; mf < 2; mf++)
                    mma16816h(acc[mf][nf], ah[mf], b0, b1);
            }
        }
    };

    // ---- prologue: zero xs (halo/OOB stay zero), stage ch0 + A(0) ----
    for (int i = tid; i < XS_BYTES/16; i += 512)
        *(uint4*)(smem + SM_XS + i*16) = make_uint4(0u,0u,0u,0u);
    __syncthreads();
    stage_x(0);
    lda(0); sta(0);
    __syncthreads();

    // ---- main loop over (ch, tap) = 18 units, A double-buffered ----
    for (int it = 0; it < 18; it++) {
        const int tap = (it < 9) ? it : it - 9;
        const int buf = it & 1;
        if (it < 17) lda(it + 1);
        compute(tap, buf);
        if (it == 8) {
            __syncthreads();          // all warps done reading xs(ch0)
            stage_x(1);
            sta(buf ^ 1);
            __syncthreads();
        } else if (it < 17) {
            sta(buf ^ 1);
            __syncthreads();
        }
    }

    // ---- epilogue: d-frag -> gmem (float2 stores) ----
    const int y = y0 + yl;
    #pragma unroll
    for (int mf = 0; mf < 2; mf++) {
        const int oc = oc0 + mw*32 + mf*16 + qr;
        float* op0 = out + (((size_t)(b*OC + oc    )*HW) + y)*HW;
        float* op1 = out + (((size_t)(b*OC + oc + 8)*HW) + y)*HW;
        #pragma unroll
        for (int nf = 0; nf < 8; nf++) {
            const int xp = nf*8 + qc*2;
            *(float2*)&op0[xp] = make_float2(acc[mf][nf][0], acc[mf][nf][1]);
            *(float2*)&op1[xp] = make_float2(acc[mf][nf][2], acc[mf][nf][3]);
        }
    }
}

// ---------------------------------------------------------------------------
extern "C" void kernel_launch(void* const* d_in, const int* in_sizes, int n_in,
                              void* d_out, int out_size)
{
    const float* x    = (const float*)d_in[0];  // [16,128,64,64]
    const float* z    = (const float*)d_in[1];  // [16,256]
    const float* bw   = (const float*)d_in[2];  // [256,128,3,3]
    const float* hw   = (const float*)d_in[3];  // [294912,256]
    float*       out  = (float*)d_out;          // [16,256,64,64]

    static bool attr_set = false;
    if (!attr_set) {
        cudaFuncSetAttribute(conv_mma, cudaFuncAttributeMaxDynamicSharedMemorySize, CONV_SMEM);
        attr_set = true;
    }

    gemm_hmma<<<NTOT/64, 256>>>(z, hw);
    build_w<<<BATCH*OC, 128>>>(bw);
    conv_mma<<<dim3(16, 2, BATCH), 512, CONV_SMEM>>>(x, out);
}

// round 9
// speedup vs baseline: 2.8270x; 1.0219x over previous
#include <cuda_runtime.h>
#include <cuda_fp16.h>
#include <cstdint>
#include <math.h>

#define BATCH 16
#define ZD 256
#define OC 256
#define IC 128
#define FANIN (IC*9)          // 1152
#define NTOT (OC*FANIN)       // 294912
#define HW 64

// ---------------- device scratch (no allocation APIs) ----------------
__device__ float g_dw[BATCH*NTOT];             // delta_w [b][n]
__device__ __half g_wh[BATCH*OC*9*IC];         // weights fp16, [b][oc][tap][cin]

// fp16 mma.sync (sm_80-era PTX — valid on plain compute_103 virtual arch)
__device__ __forceinline__ void mma16816h(float* d, const uint32_t* a,
                                          uint32_t b0, uint32_t b1) {
    asm volatile(
        "mma.sync.aligned.m16n8k16.row.col.f32.f16.f16.f32 "
        "{%0,%1,%2,%3}, {%4,%5,%6,%7}, {%8,%9}, {%0,%1,%2,%3};"
        : "+f"(d[0]), "+f"(d[1]), "+f"(d[2]), "+f"(d[3])
        : "r"(a[0]), "r"(a[1]), "r"(a[2]), "r"(a[3]), "r"(b0), "r"(b1));
}

__device__ __forceinline__ uint32_t pack_h2(float a, float b) {
    __half2 h = __floats2half2_rn(a, b);
    return *reinterpret_cast<uint32_t*>(&h);
}

// ---------------------------------------------------------------------------
// Kernel A: delta[b][n] = sum_k z[b][k] * head_w[n][k]  via HMMA.
// No B staging: B fragments gathered directly from gmem (sector-coalesced —
// each quad's 2 LDG.64 cover one 32B sector of a row). z A-frags in smem.
// Block: 64-n tile, 256 threads = 8 warps, warp = one n8 strip over K=256.
// ---------------------------------------------------------------------------
__global__ void __launch_bounds__(256) gemm_hmma(const float* __restrict__ z,
                                                 const float* __restrict__ hw)
{
    __shared__ uint4 zf[512];            // A-frags: [kk(16)][lane(32)] x 16B

    const int tid = threadIdx.x;
    const int n0  = blockIdx.x * 64;

    // ---- build z A-fragments (16 kk x 32 lanes) ----
    #pragma unroll
    for (int u = 0; u < 2; u++) {
        const int s  = tid + u*256;
        const int kk = s >> 5, l = s & 31;
        const int m  = l >> 2;
        const int kb = kk*16 + 2*(l & 3);
        float2 f0 = *(const float2*)&z[m*ZD + kb];
        float2 f1 = *(const float2*)&z[(m+8)*ZD + kb];
        float2 f2 = *(const float2*)&z[m*ZD + kb + 8];
        float2 f3 = *(const float2*)&z[(m+8)*ZD + kb + 8];
        uint4 v;
        v.x = pack_h2(f0.x, f0.y);
        v.y = pack_h2(f1.x, f1.y);
        v.z = pack_h2(f2.x, f2.y);
        v.w = pack_h2(f3.x, f3.y);
        zf[s] = v;
    }
    __syncthreads();

    const int wid = tid >> 5, lane = tid & 31;
    const int qr = lane >> 2, qc = lane & 3;
    const int row = n0 + wid*8 + qr;
    const float* rp = hw + (size_t)row*ZD + 2*qc;

    float d[4] = {0.f, 0.f, 0.f, 0.f};

    #pragma unroll
    for (int half = 0; half < 2; half++) {
        // hoist 8 kk of B (16 LDG.64 in flight)
        float2 bf0[8], bf1[8];
        #pragma unroll
        for (int kk = 0; kk < 8; kk++) {
            bf0[kk] = *(const float2*)&rp[(half*8 + kk)*16];
            bf1[kk] = *(const float2*)&rp[(half*8 + kk)*16 + 8];
        }
        #pragma unroll
        for (int kk = 0; kk < 8; kk++) {
            uint4 a = zf[(half*8 + kk)*32 + lane];
            mma16816h(d, (const uint32_t*)&a,
                      pack_h2(bf0[kk].x, bf0[kk].y),
                      pack_h2(bf1[kk].x, bf1[kk].y));
        }
    }

    const int n = n0 + wid*8 + 2*qc;
    *(float2*)&g_dw[(size_t)qr*NTOT + n]       = make_float2(d[0], d[1]);
    *(float2*)&g_dw[(size_t)(qr + 8)*NTOT + n] = make_float2(d[2], d[3]);
}

// ---------------------------------------------------------------------------
// Kernel B: standardize + build weights, emit fp16, [b][oc][tap][cin].
// Transpose via smem so global writes are coalesced 8B stores.
// ---------------------------------------------------------------------------
__global__ void __launch_bounds__(128) build_w(const float* __restrict__ base)
{
    __shared__ __half ws[FANIN];        // [tap][cin]

    const int b  = blockIdx.x >> 8;
    const int oc = blockIdx.x & 255;
    const int tid = threadIdx.x;

    const float* dwp = &g_dw[(size_t)b*NTOT + oc*FANIN];

    float v[9];
    float s = 0.f, sq = 0.f;
    #pragma unroll
    for (int t = 0; t < 9; t++) {
        v[t] = dwp[tid + t*128];
        s  += v[t];
        sq += v[t]*v[t];
    }
    #pragma unroll
    for (int off = 16; off; off >>= 1) {
        s  += __shfl_xor_sync(0xffffffffu, s,  off);
        sq += __shfl_xor_sync(0xffffffffu, sq, off);
    }
    __shared__ float ss[4], ssq[4];
    const int wid = tid >> 5;
    if ((tid & 31) == 0) { ss[wid] = s; ssq[wid] = sq; }
    __syncthreads();
    s  = ss[0] + ss[1] + ss[2] + ss[3];
    sq = ssq[0] + ssq[1] + ssq[2] + ssq[3];

    const float inv_n = 1.0f / (float)FANIN;
    float mu  = s * inv_n;
    float var = sq * inv_n - mu*mu;
    float rs  = rsqrtf(var + 1e-5f);
    const float inv_sqrt2 = 0.70710678118654752440f;
    float c1 = rs * sqrtf(2.0f / (float)FANIN) * inv_sqrt2;

    const float* bw = &base[(size_t)oc*FANIN];
    #pragma unroll
    for (int t = 0; t < 9; t++) {
        int i = tid + t*128;           // i = cin*9 + tap
        int cin = i / 9, tap = i - cin*9;
        float w = bw[i]*inv_sqrt2 + (v[t] - mu)*c1;
        ws[tap*IC + cin] = __float2half(w);
    }
    __syncthreads();

    // coalesced flush: 1152 halves = 288 x 8B
    uint2* dst = (uint2*)&g_wh[(size_t)(b*OC + oc)*9*IC];
    const uint2* src = (const uint2*)ws;
    #pragma unroll
    for (int i = tid; i < 288; i += 128) dst[i] = src[i];
}

// ---------------------------------------------------------------------------
// Kernel C: implicit-GEMM conv via mma.sync fp16 single-pass, fp32 accum.
// CTA = (4 y-rows, 128-oc tile, b). 512 threads = 16 warps, warp tile 32oc x 64n.
// R6 layout (LDS.32 fragment loads — measured at the HMMA-rate ceiling).
// ---------------------------------------------------------------------------
#define XS_STRIDE 144                  // bytes per (y,x) row of 64 cin fp16 (+16B pad)
#define XS_BYTES  (6*66*XS_STRIDE)     // 57024
#define A_BUF     18432                // one A buffer: 128 oc x 144B
#define SM_XS     36864                // after 2 A buffers
#define CONV_SMEM (SM_XS + XS_BYTES)   // 93888

__global__ void __launch_bounds__(512, 1) conv_mma(const float* __restrict__ x,
                                                   float* __restrict__ out)
{
    extern __shared__ char smem[];
    const int tid  = threadIdx.x;
    const int wid  = tid >> 5;
    const int lane = tid & 31;
    const int y0   = blockIdx.x * 4;
    const int oc0  = blockIdx.y * 128;
    const int b    = blockIdx.z;

    const int mw = wid & 3;       // oc quarter (32)
    const int yl = wid >> 2;      // local y row
    const int qr = lane >> 2;     // 0..7
    const int qc = lane & 3;      // 0..3

    float acc[2][8][4];
    #pragma unroll
    for (int mf = 0; mf < 2; mf++)
        #pragma unroll
        for (int nf = 0; nf < 8; nf++)
            #pragma unroll
            for (int q = 0; q < 4; q++) acc[mf][nf][q] = 0.f;

    uint4 nv[2];   // in-flight A tile, 2 chunks per thread

    // ---- helpers ----
    auto lda = [&](int it) {
        const int ch = it / 9, tap = it - ch*9;
        const size_t abase = ((size_t)((b*OC + oc0)*9 + tap))*IC + (size_t)ch*64;
        #pragma unroll
        for (int u = 0; u < 2; u++) {
            const int i = tid + u*512;
            const int row = i >> 3, j = i & 7;
            const size_t off8 = (abase + (size_t)row*(9*IC)) / 8 + j;   // uint4 idx
            nv[u] = ((const uint4*)g_wh)[off8];
        }
    };
    auto sta = [&](int buf) {
        char* base = smem + buf*A_BUF;
        #pragma unroll
        for (int u = 0; u < 2; u++) {
            const int i = tid + u*512;
            const int row = i >> 3, j = i & 7;
            *(uint4*)(base + row*XS_STRIDE + j*16) = nv[u];
        }
    };
    auto stage_x = [&](int ch) {
        for (int i = tid; i < 6*32*16; i += 512) {
            const int ys  = i >> 9;
            const int rem = i & 511;
            const int cp  = rem >> 4;      // c-pair 0..31
            const int x4  = rem & 15;
            const int gy  = y0 - 1 + ys;
            if (gy >= 0 && gy < HW) {
                const float4 v0 = *(const float4*)
                    &x[(((size_t)(b*IC + ch*64 + cp*2    ))*HW + gy)*HW + x4*4];
                const float4 v1 = *(const float4*)
                    &x[(((size_t)(b*IC + ch*64 + cp*2 + 1))*HW + gy)*HW + x4*4];
                const float f0[4] = {v0.x, v0.y, v0.z, v0.w};
                const float f1[4] = {v1.x, v1.y, v1.z, v1.w};
                #pragma unroll
                for (int q = 0; q < 4; q++) {
                    __half2 h = __floats2half2_rn(f0[q], f1[q]);
                    *(__half2*)(smem + SM_XS + (ys*66 + x4*4 + q + 1)*XS_STRIDE + cp*4) = h;
                }
            }
        }
    };
    auto compute = [&](int tap, int buf) {
        const int r = tap / 3, s = tap - r*3;
        const char* Ah = smem + buf*A_BUF;
        const int a_row0 = (mw*32 + qr)*XS_STRIDE + qc*4;
        const int bbase  = ((yl + r)*66 + s + qr)*XS_STRIDE + qc*4;
        #pragma unroll
        for (int ks = 0; ks < 4; ks++) {
            const int kb = ks*32;
            uint32_t ah[2][4];
            #pragma unroll
            for (int mf = 0; mf < 2; mf++) {
                const int ar = a_row0 + mf*(16*XS_STRIDE) + kb;
                ah[mf][0] = *(const uint32_t*)(Ah + ar);
                ah[mf][1] = *(const uint32_t*)(Ah + ar + 8*XS_STRIDE);
                ah[mf][2] = *(const uint32_t*)(Ah + ar + 16);
                ah[mf][3] = *(const uint32_t*)(Ah + ar + 8*XS_STRIDE + 16);
            }
            #pragma unroll
            for (int nf = 0; nf < 8; nf++) {
                const int ba = bbase + nf*(8*XS_STRIDE) + kb;
                const uint32_t b0 = *(const uint32_t*)(smem + SM_XS + ba);
                const uint32_t b1 = *(const uint32_t*)(smem + SM_XS + ba + 16);
                #pragma unroll
                for (int mf = 0; mf < 2; mf++)
                    mma16816h(acc[mf][nf], ah[mf], b0, b1);
            }
        }
    };

    // ---- prologue: zero xs (halo/OOB stay zero), stage ch0 + A(0) ----
    for (int i = tid; i < XS_BYTES/16; i += 512)
        *(uint4*)(smem + SM_XS + i*16) = make_uint4(0u,0u,0u,0u);
    __syncthreads();
    stage_x(0);
    lda(0); sta(0);
    __syncthreads();

    // ---- main loop over (ch, tap) = 18 units, A double-buffered ----
    for (int it = 0; it < 18; it++) {
        const int tap = (it < 9) ? it : it - 9;
        const int buf = it & 1;
        if (it < 17) lda(it + 1);
        compute(tap, buf);
        if (it == 8) {
            __syncthreads();          // all warps done reading xs(ch0)
            stage_x(1);
            sta(buf ^ 1);
            __syncthreads();
        } else if (it < 17) {
            sta(buf ^ 1);
            __syncthreads();
        }
    }

    // ---- epilogue: d-frag -> gmem (float2 stores) ----
    const int y = y0 + yl;
    #pragma unroll
    for (int mf = 0; mf < 2; mf++) {
        const int oc = oc0 + mw*32 + mf*16 + qr;
        float* op0 = out + (((size_t)(b*OC + oc    )*HW) + y)*HW;
        float* op1 = out + (((size_t)(b*OC + oc + 8)*HW) + y)*HW;
        #pragma unroll
        for (int nf = 0; nf < 8; nf++) {
            const int xp = nf*8 + qc*2;
            *(float2*)&op0[xp] = make_float2(acc[mf][nf][0], acc[mf][nf][1]);
            *(float2*)&op1[xp] = make_float2(acc[mf][nf][2], acc[mf][nf][3]);
        }
    }
}

// ---------------------------------------------------------------------------
extern "C" void kernel_launch(void* const* d_in, const int* in_sizes, int n_in,
                              void* d_out, int out_size)
{
    const float* x    = (const float*)d_in[0];  // [16,128,64,64]
    const float* z    = (const float*)d_in[1];  // [16,256]
    const float* bw   = (const float*)d_in[2];  // [256,128,3,3]
    const float* hw   = (const float*)d_in[3];  // [294912,256]
    float*       out  = (float*)d_out;          // [16,256,64,64]

    static bool attr_set = false;
    if (!attr_set) {
        cudaFuncSetAttribute(conv_mma, cudaFuncAttributeMaxDynamicSharedMemorySize, CONV_SMEM);
        attr_set = true;
    }

    gemm_hmma<<<NTOT/64, 256>>>(z, hw);
    build_w<<<BATCH*OC, 128>>>(bw);
    conv_mma<<<dim3(16, 2, BATCH), 512, CONV_SMEM>>>(x, out);
}